// round 1
// baseline (speedup 1.0000x reference)
#include <cuda_runtime.h>

// Temporal-blocked persistent solver:
//   - Each block owns TILE=4096 grid points + HALO=128 on each side (L=4352 local points).
//   - 256 threads/block, 17 points/thread, all state in registers.
//   - Per step: pass1 computes fluxes per point; edge values (rho,v,f_mass,f_mom)
//     cross thread boundaries via shared memory; pass2 does the LxF update.
//   - Contamination from the (unexchanged) block edges advances exactly 1 cell/step,
//     so after 128 steps the interior TILE region is exact.

#define NT   256
#define PPT  17
#define LBUF (NT * PPT)            // 4352
#define HALO 128
#define TILE (LBUF - 2 * HALO)     // 4096

__global__ __launch_bounds__(NT, 2)
void obf_solver_kernel(const float* __restrict__ rho0,
                       const float* __restrict__ v0,
                       const int*   __restrict__ n_steps_ptr,
                       float*       __restrict__ out,
                       int N)
{
    __shared__ float sLR[NT], sLV[NT], sLFm[NT], sLFp[NT];   // last point of each thread
    __shared__ float sFR[NT], sFV[NT], sFFm[NT], sFFp[NT];   // first point of each thread

    const int t = threadIdx.x;
    const int b = blockIdx.x;
    const int base = b * TILE - HALO + t * PPT;   // local start in global coords (may be <0 or >=N)

    float rho[PPT], v[PPT], fm[PPT], fp[PPT];

    // Load initial state (periodic wrap)
    #pragma unroll
    for (int j = 0; j < PPT; ++j) {
        int g = base + j + N;            // in [N-HALO, 2N+HALO)
        if (g >= N) g -= N;
        if (g >= N) g -= N;
        rho[j] = rho0[g];
        v[j]   = v0[g];
    }

    const int n_steps = *n_steps_ptr;

    const float C1 = 0.005f;   // DT / (2*DX)
    const float C2 = 0.01f;    // DT * MU / DX^2
    const float GAM = 1.4f;

    for (int s = 0; s < n_steps; ++s) {
        // ---- pass 1: pointwise fluxes ----
        #pragma unroll
        for (int j = 0; j < PPT; ++j) {
            float P = __powf(fmaxf(rho[j], 0.0f), GAM);
            fm[j] = rho[j] * v[j];                 // mass flux == momentum
            fp[j] = fmaf(fm[j], v[j], P);          // momentum flux
        }

        // ---- edge exchange between threads ----
        sLR[t]  = rho[PPT - 1]; sLV[t]  = v[PPT - 1];
        sLFm[t] = fm[PPT - 1];  sLFp[t] = fp[PPT - 1];
        sFR[t]  = rho[0];       sFV[t]  = v[0];
        sFFm[t] = fm[0];        sFFp[t] = fp[0];
        __syncthreads();

        const int lt = (t == 0)      ? 0      : t - 1;
        const int rt = (t == NT - 1) ? NT - 1 : t + 1;
        float pR = sLR[lt],  pV = sLV[lt],  pFm = sLFm[lt], pFp = sLFp[lt];
        float rR = sFR[rt],  rV = sFV[rt],  rFm = sFFm[rt], rFp = sFFp[rt];
        __syncthreads();   // reads latched into registers; shared is free for next step

        // ---- pass 2: LxF update ----
        #pragma unroll
        for (int j = 0; j < PPT; ++j) {
            const bool last = (j == PPT - 1);
            float nR  = last ? rR  : rho[j + 1];
            float nV  = last ? rV  : v[j + 1];
            float nFm = last ? rFm : fm[j + 1];
            float nFp = last ? rFp : fp[j + 1];

            float rnew = 0.5f * (nR + pR) - C1 * (nFm - pFm);
            float visc = (nV + pV) - 2.0f * v[j];
            float mnew = 0.5f * (nFm + pFm) - C1 * (nFp - pFp) + (C2 * rho[j]) * visc;
            float vnew = __fdividef(mnew, fmaxf(rnew, 1e-10f));

            pR = rho[j]; pV = v[j]; pFm = fm[j]; pFp = fp[j];
            rho[j] = rnew; v[j] = vnew;
        }
    }

    // ---- store the valid interior region ----
    float* out_rho = out;
    float* out_v   = out + N;
    #pragma unroll
    for (int j = 0; j < PPT; ++j) {
        int l = t * PPT + j;                 // local index in [0, LBUF)
        if (l >= HALO && l < LBUF - HALO) {
            int g = b * TILE + (l - HALO);   // always in [0, N)
            out_rho[g] = rho[j];
            out_v[g]   = v[j];
        }
    }
}

extern "C" void kernel_launch(void* const* d_in, const int* in_sizes, int n_in,
                              void* d_out, int out_size)
{
    const float* rho0   = (const float*)d_in[0];
    const float* v0     = (const float*)d_in[1];
    const int*   nsteps = (const int*)d_in[2];
    float*       out    = (float*)d_out;

    const int N = in_sizes[0];          // 1048576 for this problem
    const int blocks = N / TILE;        // 256

    obf_solver_kernel<<<blocks, NT>>>(rho0, v0, nsteps, out, N);
}